// round 3
// baseline (speedup 1.0000x reference)
#include <cuda_runtime.h>

// out[b, :] = table_bits[idx(b), :],  idx(b) = sum_k idx_bits[b,k] << (5-k)
// table_bits: [64,64] f32 (16 KB, values are 0.0/1.0), idx_bits: [262144,6] i32,
// out: [262144,64] f32 (64 MB). Pure streaming: floor = DRAM drain of output.

#define BATCH   262144
#define THREADS 512                 // 16 warps / block
#define CHUNKS_PER_THREAD 4         // each chunk = 32 B (2 float4) of one row

// chunks total = BATCH*8 ; threads = chunks/4 ; blocks = threads/512
#define GRID ((BATCH * 8) / (THREADS * CHUNKS_PER_THREAD))   // 1024

__global__ __launch_bounds__(THREADS)
void spike_lookup_kernel(const float4* __restrict__ table4,  // 64*16 float4
                         const int*    __restrict__ bits,    // BATCH*6
                         float4*       __restrict__ out4)    // BATCH*16
{
    __shared__ float4 t[64 * 16];   // 16 KB table; row r at t[r*16 .. r*16+15]

    #pragma unroll
    for (int i = threadIdx.x; i < 64 * 16; i += THREADS)
        t[i] = table4[i];
    __syncthreads();

    const int lane  = threadIdx.x & 31;
    const int gwarp = blockIdx.x * (THREADS / 32) + (threadIdx.x >> 5);

    // This warp covers 16 batch rows -> 96 index ints, fully coalesced.
    const int* __restrict__ p = bits + gwarp * 96;
    int v0 = p[lane];
    int v1 = p[lane + 32];
    int v2 = p[lane + 64];
    unsigned b0 = __ballot_sync(0xFFFFFFFFu, v0 != 0);  // int i -> bit i
    unsigned b1 = __ballot_sync(0xFFFFFFFFu, v1 != 0);
    unsigned b2 = __ballot_sync(0xFFFFFFFFu, v2 != 0);

    unsigned long long u01 = (unsigned long long)b0 | ((unsigned long long)b1 << 32);
    unsigned long long u12 = (unsigned long long)b1 | ((unsigned long long)b2 << 32);

    const int jj = lane & 7;                 // which 32B octet within the 64-float row
    const int rbase = lane >> 3;             // 0..3

    #pragma unroll
    for (int i = 0; i < CHUNKS_PER_THREAD; i++) {
        int r = i * 4 + rbase;               // local row 0..15 within this warp
        int sh = 6 * r;
        unsigned vbits = (r < 10) ? (unsigned)(u01 >> sh)
                                  : (unsigned)(u12 >> (sh - 32));
        vbits &= 63u;                        // bit0 = MSB-weight bit (k=0, weight 32)
        int idx = (int)(__brev(vbits) >> 26);  // reverse 6 bits -> table row

        const float4* __restrict__ src = &t[idx * 16 + jj * 2];
        float4 o0 = src[0];
        float4 o1 = src[1];

        // chunk id: gwarp*128 + i*32 + lane ; float4 index = chunk*2
        long long f4 = ((long long)gwarp * 128 + i * 32 + lane) * 2;
        out4[f4]     = o0;
        out4[f4 + 1] = o1;
    }
}

extern "C" void kernel_launch(void* const* d_in, const int* in_sizes, int n_in,
                              void* d_out, int out_size)
{
    const float4* table4 = (const float4*)d_in[0];
    const int*    bits   = (const int*)d_in[1];
    float4*       out4   = (float4*)d_out;

    spike_lookup_kernel<<<GRID, THREADS>>>(table4, bits, out4);
}

// round 4
// speedup vs baseline: 1.5233x; 1.5233x over previous
#include <cuda_runtime.h>

// out[b, :] = table_bits[idx(b), :],  idx(b) = sum_k idx_bits[b,k] << (5-k)
// table_bits: [64,64] f32 (16 KB), idx_bits: [262144,6] i32, out: [262144,64] f32.
//
// Warp w owns 16 consecutive batch rows (4 KB of output = 256 float4).
// Per warp: 3 coalesced LDG.32 + 3 ballots to gather all 96 index bits,
// then 8 iterations of {conflict-free LDS.128 from smem table, contiguous STG.128}.

#define BATCH   262144
#define THREADS 512                                  // 16 warps / block
#define ROWS_PER_WARP 16
#define GRID (BATCH / (ROWS_PER_WARP * (THREADS/32)))   // 1024 blocks

__global__ __launch_bounds__(THREADS)
void spike_lookup_kernel(const float4* __restrict__ table4,  // 64*16 float4
                         const int*    __restrict__ bits,    // BATCH*6
                         float4*       __restrict__ out4)    // BATCH*16
{
    __shared__ float4 t[64 * 16];     // 16 KB; row r at t[r*16 .. r*16+15]

    #pragma unroll
    for (int i = threadIdx.x; i < 64 * 16; i += THREADS)
        t[i] = table4[i];
    __syncthreads();

    const int lane  = threadIdx.x & 31;
    const int gwarp = blockIdx.x * (THREADS / 32) + (threadIdx.x >> 5);

    // 16 rows * 6 ints = 96 ints, fully coalesced.
    const int* __restrict__ p = bits + gwarp * 96;
    unsigned b0 = __ballot_sync(0xFFFFFFFFu, p[lane]      != 0); // int m -> bit m
    unsigned b1 = __ballot_sync(0xFFFFFFFFu, p[lane + 32] != 0);
    unsigned b2 = __ballot_sync(0xFFFFFFFFu, p[lane + 64] != 0);

    unsigned long long u01 = (unsigned long long)b0 | ((unsigned long long)b1 << 32);
    unsigned long long u12 = (unsigned long long)b1 | ((unsigned long long)b2 << 32);

    const int j    = lane & 15;        // float4 column within the 64-float row
    const int half = lane >> 4;        // 0: even local row, 1: odd local row

    float4* __restrict__ dst = out4 + (long long)gwarp * 256 + lane;

    #pragma unroll
    for (int i = 0; i < 8; i++) {
        int r  = 2 * i + half;                    // local row 0..15
        int sh = 6 * r;                           // bit offset of this row's 6 bits
        unsigned vb = (r < 10) ? (unsigned)(u01 >> sh)
                               : (unsigned)(u12 >> (sh - 32));
        int idx = (int)(__brev(vb & 63u) >> 26);  // k=0 is MSB (weight 32)

        dst[i * 32] = t[idx * 16 + j];            // contiguous 512B STG per warp
    }
}

extern "C" void kernel_launch(void* const* d_in, const int* in_sizes, int n_in,
                              void* d_out, int out_size)
{
    const float4* table4 = (const float4*)d_in[0];
    const int*    bits   = (const int*)d_in[1];
    float4*       out4   = (float4*)d_out;

    spike_lookup_kernel<<<GRID, THREADS>>>(table4, bits, out4);
}